// round 9
// baseline (speedup 1.0000x reference)
#include <cuda_runtime.h>
#include <math.h>

// Problem constants
#define PB     32
#define PN     325
#define PK     20
#define S_IN   12
#define S_OUT  12
#define PC     10
#define H48    48
#define BN     (PB * PN)                 // 10400 nodes
#define OUT_DATA_ELEMS (BN * PC * S_OUT) // 1,248,000

#define MAIN_CTAS       650
#define MAIN_WARPS      4                // 128-thread CTAs
#define NODES_PER_WARP  4                // 650*4*4 = 10400 exact

// ---------------- scratch (no allocation allowed) ----------------
__device__ __align__(16) float  g_wh [BN * S_OUT];   // wh per node (12)
__device__ __align__(16) float  g_hxb[BN * H48];     // hx + a1_b per node (48)
__device__ __align__(16) float  g_hy [BN * H48];     // hy per node (48)
__device__ double g_acc[3];        // 0: cluster-loss sum, 1: dist sum, 2: wh sum
__device__ unsigned int g_done;    // last-block counter (self-resetting)

__device__ __forceinline__ float leaky(float x) { return x >= 0.f ? x : 0.5f * x; }

// ---------------- kernel 1: per-node precompute ----------------
// 2 threads per node (each covers 24 of the 48 hidden dims); 64 nodes / 128-thread CTA.
__global__ void __launch_bounds__(128)
k_pre(const float* __restrict__ in,
      const float* __restrict__ wW,  const float* __restrict__ wb,
      const float* __restrict__ a1W, const float* __restrict__ a1b)
{
    __shared__ float s_wW[S_IN * S_OUT];
    __shared__ float s_wb[S_OUT];
    __shared__ float s_a1W[2 * S_OUT * H48];
    __shared__ float s_a1b[H48];
    __shared__ double s_red[4];

    for (int i = threadIdx.x; i < S_IN * S_OUT;    i += 128) s_wW[i]  = wW[i];
    if (threadIdx.x < S_OUT) s_wb[threadIdx.x] = wb[threadIdx.x];
    for (int i = threadIdx.x; i < 2 * S_OUT * H48; i += 128) s_a1W[i] = a1W[i];
    if (threadIdx.x < H48) s_a1b[threadIdx.x] = a1b[threadIdx.x];
    __syncthreads();

    const int t    = threadIdx.x;
    const int node = blockIdx.x * 64 + (t >> 1);
    const int half = t & 1;
    float whsum = 0.f;

    if (node < BN) {
        const float4* xp = reinterpret_cast<const float4*>(&in[node * S_IN]);
        float4 x0 = xp[0], x1 = xp[1], x2 = xp[2];
        float x[S_IN] = {x0.x, x0.y, x0.z, x0.w, x1.x, x1.y, x1.z, x1.w,
                         x2.x, x2.y, x2.z, x2.w};

        float wh[S_OUT];
        #pragma unroll
        for (int j = 0; j < S_OUT; j++) {
            float a = s_wb[j];
            #pragma unroll
            for (int i = 0; i < S_IN; i++) a = fmaf(x[i], s_wW[i * S_OUT + j], a);
            wh[j] = leaky(a);
        }
        if (half == 0) {
            float4* wp = reinterpret_cast<float4*>(&g_wh[(size_t)node * S_OUT]);
            wp[0] = make_float4(wh[0], wh[1], wh[2], wh[3]);
            wp[1] = make_float4(wh[4], wh[5], wh[6], wh[7]);
            wp[2] = make_float4(wh[8], wh[9], wh[10], wh[11]);
            #pragma unroll
            for (int j = 0; j < S_OUT; j++) whsum += wh[j];
        }

        const int d0 = half * 24;
        #pragma unroll
        for (int dq = 0; dq < 24; dq += 4) {
            float hx[4], hy[4];
            #pragma unroll
            for (int q = 0; q < 4; q++) {
                int d = d0 + dq + q;
                float a = s_a1b[d], b = 0.f;
                #pragma unroll
                for (int j = 0; j < S_OUT; j++) {
                    a = fmaf(wh[j], s_a1W[j * H48 + d], a);
                    b = fmaf(wh[j], s_a1W[(S_OUT + j) * H48 + d], b);
                }
                hx[q] = a; hy[q] = b;
            }
            *reinterpret_cast<float4*>(&g_hxb[(size_t)node * H48 + d0 + dq]) =
                make_float4(hx[0], hx[1], hx[2], hx[3]);
            *reinterpret_cast<float4*>(&g_hy [(size_t)node * H48 + d0 + dq]) =
                make_float4(hy[0], hy[1], hy[2], hy[3]);
        }
    }

    #pragma unroll
    for (int o = 16; o > 0; o >>= 1) whsum += __shfl_down_sync(0xffffffffu, whsum, o);
    int warp = threadIdx.x >> 5, lane = threadIdx.x & 31;
    if (lane == 0) s_red[warp] = (double)whsum;
    __syncthreads();
    if (threadIdx.x == 0)
        atomicAdd(&g_acc[2], s_red[0] + s_red[1] + s_red[2] + s_red[3]);
}

// ---------------- kernel 2: warp-per-node main (4 nodes/warp) ----------------
struct WS {
    float4 wtn[PK * 5];        // normalized wh rows, stride 20 floats (bank-free)
    float4 am [PK * 3];        // softmaxed attention rows, stride 12 (pads = 0)
    float  amT[PC * PK];       // transposed: amT[c][k]
    float  whkT[S_OUT * PK];   // transposed: whkT[s][k] (un-normalized)
};

__global__ void __launch_bounds__(32 * MAIN_WARPS)
k_main(const int* __restrict__ idx,
       const float* __restrict__ a2W, const float* __restrict__ a2b,
       float* __restrict__ out)
{
    __shared__ WS     ws[MAIN_WARPS];
    __shared__ float4 s_w2[H48 * 3];   // a2_W rows padded 10 -> 12 floats
    __shared__ float  s_b2[PC];
    __shared__ double s_red[2 * MAIN_WARPS];

    const int tid  = threadIdx.x;
    const int wid  = tid >> 5;
    const int lane = tid & 31;

    for (int d = tid; d < H48; d += 32 * MAIN_WARPS) {
        const float* src = a2W + d * PC;
        s_w2[d * 3 + 0] = make_float4(src[0], src[1], src[2], src[3]);
        s_w2[d * 3 + 1] = make_float4(src[4], src[5], src[6], src[7]);
        s_w2[d * 3 + 2] = make_float4(src[8], src[9], 0.f, 0.f);
    }
    if (tid < PC) s_b2[tid] = a2b[tid];
    __syncthreads();

    WS* w = &ws[wid];
    double clsum = 0.0, dsum = 0.0;

    #pragma unroll 1
    for (int it = 0; it < NODES_PER_WARP; it++) {
        const int node = blockIdx.x * (MAIN_WARPS * NODES_PER_WARP)
                       + wid * NODES_PER_WARP + it;
        const int base = (node / PN) * PN;

        // ---- lane k (<20): logits -> softmax; normalized wh; transposes ----
        if (lane < PK) {
            const int jn = base + idx[node * PK + lane];
            const float4* hyp = reinterpret_cast<const float4*>(&g_hy [(size_t)jn   * H48]);
            const float4* hxp = reinterpret_cast<const float4*>(&g_hxb[(size_t)node * H48]);

            float acc[PC];
            #pragma unroll
            for (int c = 0; c < PC; c++) acc[c] = s_b2[c];

            #pragma unroll
            for (int hb = 0; hb < 2; hb++) {
                float4 v[6], hx[6];
                #pragma unroll
                for (int i = 0; i < 6; i++) { v[i] = hyp[hb * 6 + i]; hx[i] = hxp[hb * 6 + i]; }
                #pragma unroll
                for (int i = 0; i < 6; i++) {
                    float hv[4]  = {v[i].x,  v[i].y,  v[i].z,  v[i].w};
                    float hxv[4] = {hx[i].x, hx[i].y, hx[i].z, hx[i].w};
                    #pragma unroll
                    for (int q = 0; q < 4; q++) {
                        const int d = hb * 24 + i * 4 + q;
                        const float h = leaky(hxv[q] + hv[q]);
                        float4 w0 = s_w2[d * 3 + 0], w1 = s_w2[d * 3 + 1], w2q = s_w2[d * 3 + 2];
                        acc[0] = fmaf(h, w0.x, acc[0]); acc[1] = fmaf(h, w0.y, acc[1]);
                        acc[2] = fmaf(h, w0.z, acc[2]); acc[3] = fmaf(h, w0.w, acc[3]);
                        acc[4] = fmaf(h, w1.x, acc[4]); acc[5] = fmaf(h, w1.y, acc[5]);
                        acc[6] = fmaf(h, w1.z, acc[6]); acc[7] = fmaf(h, w1.w, acc[7]);
                        acc[8] = fmaf(h, w2q.x, acc[8]); acc[9] = fmaf(h, w2q.y, acc[9]);
                    }
                }
            }
            // leaky + softmax
            float m = -1e30f;
            #pragma unroll
            for (int c = 0; c < PC; c++) { acc[c] = leaky(acc[c]); m = fmaxf(m, acc[c]); }
            float sum = 0.f;
            #pragma unroll
            for (int c = 0; c < PC; c++) { acc[c] = __expf(acc[c] - m); sum += acc[c]; }
            const float is = 1.f / sum;
            #pragma unroll
            for (int c = 0; c < PC; c++) acc[c] *= is;

            w->am[lane * 3 + 0] = make_float4(acc[0], acc[1], acc[2], acc[3]);
            w->am[lane * 3 + 1] = make_float4(acc[4], acc[5], acc[6], acc[7]);
            w->am[lane * 3 + 2] = make_float4(acc[8], acc[9], 0.f, 0.f);
            #pragma unroll
            for (int c = 0; c < PC; c++) w->amT[c * PK + lane] = acc[c];

            // gather wh, inv-norm, store normalized rows + transpose
            const float4* wp = reinterpret_cast<const float4*>(&g_wh[(size_t)jn * S_OUT]);
            float4 b0 = wp[0], b1 = wp[1], b2v = wp[2];
            float wr[S_OUT] = {b0.x, b0.y, b0.z, b0.w, b1.x, b1.y, b1.z, b1.w,
                               b2v.x, b2v.y, b2v.z, b2v.w};
            float n2 = 0.f;
            #pragma unroll
            for (int s = 0; s < S_OUT; s++) n2 = fmaf(wr[s], wr[s], n2);
            const float inv = 1.f / (sqrtf(n2) + 1e-8f);

            w->wtn[lane * 5 + 0] = make_float4(wr[0] * inv, wr[1] * inv, wr[2] * inv, wr[3] * inv);
            w->wtn[lane * 5 + 1] = make_float4(wr[4] * inv, wr[5] * inv, wr[6] * inv, wr[7] * inv);
            w->wtn[lane * 5 + 2] = make_float4(wr[8] * inv, wr[9] * inv, wr[10] * inv, wr[11] * inv);
            #pragma unroll
            for (int s = 0; s < S_OUT; s++) w->whkT[s * PK + lane] = wr[s];
        }
        __syncwarp();

        // ---- output: out[node,c,s] = sum_k am[k][c] * wh[k][s] (vectorized over k) ----
        {
            int c = lane / S_OUT, s = lane - c * S_OUT;
            for (int i = lane; i < PC * S_OUT; i += 32) {
                const float4* ar = reinterpret_cast<const float4*>(w->amT  + c * PK);
                const float4* br = reinterpret_cast<const float4*>(w->whkT + s * PK);
                float o = 0.f;
                #pragma unroll
                for (int q = 0; q < 5; q++) {
                    float4 a4 = ar[q], b4 = br[q];
                    o = fmaf(a4.x, b4.x, o); o = fmaf(a4.y, b4.y, o);
                    o = fmaf(a4.z, b4.z, o); o = fmaf(a4.w, b4.w, o);
                }
                out[(size_t)node * (PC * S_OUT) + i] = o;
                c += 2; s += 8; if (s >= S_OUT) { s -= S_OUT; c++; }
            }
        }

        // ---- K x K pair phase (vectorized rows) ----
        {
            float fcl = 0.f, fds = 0.f;
            int k = lane / PK, l = lane - k * PK;
            for (int p = lane; p < PK * PK; p += 32) {
                const float4* rk = &w->wtn[k * 5];
                const float4* rl = &w->wtn[l * 5];
                float4 k0 = rk[0], k1 = rk[1], k2 = rk[2];
                float4 l0 = rl[0], l1 = rl[1], l2 = rl[2];
                float dist = k0.x * l0.x;
                dist = fmaf(k0.y, l0.y, dist); dist = fmaf(k0.z, l0.z, dist);
                dist = fmaf(k0.w, l0.w, dist); dist = fmaf(k1.x, l1.x, dist);
                dist = fmaf(k1.y, l1.y, dist); dist = fmaf(k1.z, l1.z, dist);
                dist = fmaf(k1.w, l1.w, dist); dist = fmaf(k2.x, l2.x, dist);
                dist = fmaf(k2.y, l2.y, dist); dist = fmaf(k2.z, l2.z, dist);
                dist = fmaf(k2.w, l2.w, dist);
                fds += dist;
                if (k != l) {
                    const float4* ak = &w->am[k * 3];
                    const float4* al = &w->am[l * 3];
                    float4 p0 = ak[0], p1 = ak[1], p2 = ak[2];
                    float4 q0 = al[0], q1 = al[1], q2 = al[2];
                    float prob = p0.x * q0.x;
                    prob = fmaf(p0.y, q0.y, prob); prob = fmaf(p0.z, q0.z, prob);
                    prob = fmaf(p0.w, q0.w, prob); prob = fmaf(p1.x, q1.x, prob);
                    prob = fmaf(p1.y, q1.y, prob); prob = fmaf(p1.z, q1.z, prob);
                    prob = fmaf(p1.w, q1.w, prob); prob = fmaf(p2.x, q2.x, prob);
                    prob = fmaf(p2.y, q2.y, prob);   // pads are zero
                    prob = fminf(fmaxf(prob, 1e-4f), 1.f - 1e-4f);
                    const float lg = __logf(prob);
                    fcl += (dist >= 0.5f) ? -lg : lg;
                }
                l += 12; k += 1; if (l >= PK) { l -= PK; k += 1; }
            }
            clsum += (double)fcl;
            dsum  += (double)fds;
        }
        __syncwarp();   // before next node reuses this warp's smem
    }

    // ---- reduce: warp -> block -> global atomics; last CTA finalizes ----
    #pragma unroll
    for (int o = 16; o > 0; o >>= 1) {
        clsum += __shfl_down_sync(0xffffffffu, clsum, o);
        dsum  += __shfl_down_sync(0xffffffffu, dsum,  o);
    }
    if (lane == 0) { s_red[wid] = clsum; s_red[MAIN_WARPS + wid] = dsum; }
    __syncthreads();

    if (tid == 0) {
        double tc = 0.0, td = 0.0;
        #pragma unroll
        for (int q = 0; q < MAIN_WARPS; q++) { tc += s_red[q]; td += s_red[MAIN_WARPS + q]; }
        atomicAdd(&g_acc[0], tc);
        atomicAdd(&g_acc[1], td);
        __threadfence();
        unsigned int done = atomicAdd(&g_done, 1u);
        if (done == (unsigned int)(gridDim.x - 1)) {
            __threadfence();
            volatile double* acc = g_acc;
            double c0 = acc[0], c1 = acc[1], c2 = acc[2];
            out[OUT_DATA_ELEMS + 0] = (float)(c0 / (double)BN);
            out[OUT_DATA_ELEMS + 1] = (float)(c1 / ((double)BN * PK * PK));
            out[OUT_DATA_ELEMS + 2] = (float)(c2 / ((double)BN * S_OUT));
            acc[0] = 0.0; acc[1] = 0.0; acc[2] = 0.0;
            g_done = 0;
            __threadfence();
        }
    }
}

// ---------------- launch ----------------
extern "C" void kernel_launch(void* const* d_in, const int* in_sizes, int n_in,
                              void* d_out, int out_size)
{
    const float* input_data = (const float*)d_in[1];
    const float* wW  = (const float*)d_in[2];
    const float* wb  = (const float*)d_in[3];
    const float* a1W = (const float*)d_in[4];
    const float* a1b = (const float*)d_in[5];
    const float* a2W = (const float*)d_in[6];
    const float* a2b = (const float*)d_in[7];
    const int*   idx = (const int*)d_in[8];
    float* out = (float*)d_out;

    k_pre <<<(BN + 63) / 64, 128>>>(input_data, wW, wb, a1W, a1b);
    k_main<<<MAIN_CTAS, 32 * MAIN_WARPS>>>(idx, a2W, a2b, out);
}

// round 11
// speedup vs baseline: 1.2372x; 1.2372x over previous
#include <cuda_runtime.h>
#include <math.h>

// Problem constants
#define PB     32
#define PN     325
#define PK     20
#define S_IN   12
#define S_OUT  12
#define PC     10
#define H48    48
#define BN     (PB * PN)                 // 10400 nodes
#define OUT_DATA_ELEMS (BN * PC * S_OUT) // 1,248,000

#define NODES_PER_CTA  8
#define MAIN_THREADS   160               // 8 nodes * 20 k-slots, 5 warps
#define MAIN_CTAS      (BN / NODES_PER_CTA)   // 1300
#define NPAIRS         190               // K*(K-1)/2 triangle pairs

// ---------------- scratch (no allocation allowed) ----------------
__device__ __align__(16) float  g_wh [BN * S_OUT];   // wh per node (12)
__device__ __align__(16) float  g_hxb[BN * H48];     // hx + a1_b per node (48)
__device__ __align__(16) float  g_hy [BN * H48];     // hy per node (48)
__device__ double g_acc[3];        // 0: cluster-loss sum, 1: dist sum, 2: wh sum
__device__ unsigned int g_done;    // last-block counter (self-resetting)

__device__ __forceinline__ float leaky(float x) { return x >= 0.f ? x : 0.5f * x; }

// ---------------- kernel 1: per-node precompute ----------------
// 2 threads per node (24 of 48 hidden dims each); 64 nodes per 128-thread CTA.
__global__ void __launch_bounds__(128)
k_pre(const float* __restrict__ in,
      const float* __restrict__ wW,  const float* __restrict__ wb,
      const float* __restrict__ a1W, const float* __restrict__ a1b)
{
    __shared__ float s_wW[S_IN * S_OUT];
    __shared__ float s_wb[S_OUT];
    __shared__ float s_a1W[2 * S_OUT * H48];
    __shared__ float s_a1b[H48];
    __shared__ double s_red[4];

    for (int i = threadIdx.x; i < S_IN * S_OUT;    i += 128) s_wW[i]  = wW[i];
    if (threadIdx.x < S_OUT) s_wb[threadIdx.x] = wb[threadIdx.x];
    for (int i = threadIdx.x; i < 2 * S_OUT * H48; i += 128) s_a1W[i] = a1W[i];
    if (threadIdx.x < H48) s_a1b[threadIdx.x] = a1b[threadIdx.x];
    __syncthreads();

    const int t    = threadIdx.x;
    const int node = blockIdx.x * 64 + (t >> 1);
    const int half = t & 1;
    float whsum = 0.f;

    if (node < BN) {
        const float4* xp = reinterpret_cast<const float4*>(&in[node * S_IN]);
        float4 x0 = xp[0], x1 = xp[1], x2 = xp[2];
        float x[S_IN] = {x0.x, x0.y, x0.z, x0.w, x1.x, x1.y, x1.z, x1.w,
                         x2.x, x2.y, x2.z, x2.w};

        float wh[S_OUT];
        #pragma unroll
        for (int j = 0; j < S_OUT; j++) {
            float a = s_wb[j];
            #pragma unroll
            for (int i = 0; i < S_IN; i++) a = fmaf(x[i], s_wW[i * S_OUT + j], a);
            wh[j] = leaky(a);
        }
        if (half == 0) {
            float4* wp = reinterpret_cast<float4*>(&g_wh[(size_t)node * S_OUT]);
            wp[0] = make_float4(wh[0], wh[1], wh[2], wh[3]);
            wp[1] = make_float4(wh[4], wh[5], wh[6], wh[7]);
            wp[2] = make_float4(wh[8], wh[9], wh[10], wh[11]);
            #pragma unroll
            for (int j = 0; j < S_OUT; j++) whsum += wh[j];
        }

        const int d0 = half * 24;
        #pragma unroll
        for (int dq = 0; dq < 24; dq += 4) {
            float hx[4], hy[4];
            #pragma unroll
            for (int q = 0; q < 4; q++) {
                int d = d0 + dq + q;
                float a = s_a1b[d], b = 0.f;
                #pragma unroll
                for (int j = 0; j < S_OUT; j++) {
                    a = fmaf(wh[j], s_a1W[j * H48 + d], a);
                    b = fmaf(wh[j], s_a1W[(S_OUT + j) * H48 + d], b);
                }
                hx[q] = a; hy[q] = b;
            }
            *reinterpret_cast<float4*>(&g_hxb[(size_t)node * H48 + d0 + dq]) =
                make_float4(hx[0], hx[1], hx[2], hx[3]);
            *reinterpret_cast<float4*>(&g_hy [(size_t)node * H48 + d0 + dq]) =
                make_float4(hy[0], hy[1], hy[2], hy[3]);
        }
    }

    #pragma unroll
    for (int o = 16; o > 0; o >>= 1) whsum += __shfl_down_sync(0xffffffffu, whsum, o);
    int warp = threadIdx.x >> 5, lane = threadIdx.x & 31;
    if (lane == 0) s_red[warp] = (double)whsum;
    __syncthreads();
    if (threadIdx.x == 0)
        atomicAdd(&g_acc[2], s_red[0] + s_red[1] + s_red[2] + s_red[3]);
}

// ---------------- kernel 2: thread-per-(node,k) main ----------------
struct __align__(16) NodeS {
    float wh [PK][20];   // rows: 12 data + pad to 20 floats (80B, phase-conflict-free)
    float am [PK][12];   // rows: 10 data + 2 zero pads (48B)
    float inv[PK];
};

__global__ void __launch_bounds__(MAIN_THREADS, 8)
k_main(const int* __restrict__ idx,
       const float* __restrict__ a2W, const float* __restrict__ a2b,
       float* __restrict__ out)
{
    __shared__ NodeS  nodes[NODES_PER_CTA];           // ~21 KB
    __shared__ float4 s_w2[H48 * 3];                  // a2_W rows padded 10 -> 12
    __shared__ float  s_b2[PC];
    __shared__ float4 s_hx4[NODES_PER_CTA * 12];      // hx rows for the 8 nodes
    __shared__ unsigned short s_tbl[NPAIRS];          // packed (k<<5)|l, k<l
    __shared__ double s_redc[5], s_redd[5];

    const int tid  = threadIdx.x;
    const int wid  = tid >> 5;
    const int lane = tid & 31;
    const int nl   = tid / PK;            // 0..7 node-local
    const int k    = tid - nl * PK;       // 0..19
    const int node = blockIdx.x * NODES_PER_CTA + nl;
    const int base = (node / PN) * PN;

    // ---- stage weights, bias, pair table, hx rows ----
    for (int d = tid; d < H48; d += MAIN_THREADS) {
        const float* src = a2W + d * PC;
        s_w2[d * 3 + 0] = make_float4(src[0], src[1], src[2], src[3]);
        s_w2[d * 3 + 1] = make_float4(src[4], src[5], src[6], src[7]);
        s_w2[d * 3 + 2] = make_float4(src[8], src[9], 0.f, 0.f);
    }
    if (tid < PC) s_b2[tid] = a2b[tid];
    for (int i = tid; i < NPAIRS; i += MAIN_THREADS) {
        int kk = 0, rem = i;
        while (rem >= PK - 1 - kk) { rem -= PK - 1 - kk; kk++; }
        s_tbl[i] = (unsigned short)((kk << 5) | (kk + 1 + rem));
    }
    for (int i = tid; i < NODES_PER_CTA * 12; i += MAIN_THREADS) {
        int n = i / 12, q = i - n * 12;
        s_hx4[i] = reinterpret_cast<const float4*>(
            g_hxb + (size_t)(blockIdx.x * NODES_PER_CTA + n) * H48)[q];
    }
    __syncthreads();

    double ddsum = 0.0;   // diagonal dist contribution

    // ================= phase 1: one thread = one (node, k) =================
    {
        const int jn = base + idx[node * PK + k];
        const float4* hyp = reinterpret_cast<const float4*>(&g_hy[(size_t)jn * H48]);

        float acc[PC];
        #pragma unroll
        for (int c = 0; c < PC; c++) acc[c] = s_b2[c];

        #pragma unroll
        for (int ch = 0; ch < 4; ch++) {
            float4 y0 = hyp[ch * 3 + 0], y1 = hyp[ch * 3 + 1], y2 = hyp[ch * 3 + 2];
            float4 x0 = s_hx4[nl * 12 + ch * 3 + 0];
            float4 x1 = s_hx4[nl * 12 + ch * 3 + 1];
            float4 x2 = s_hx4[nl * 12 + ch * 3 + 2];
            float h[12] = {
                leaky(x0.x + y0.x), leaky(x0.y + y0.y), leaky(x0.z + y0.z), leaky(x0.w + y0.w),
                leaky(x1.x + y1.x), leaky(x1.y + y1.y), leaky(x1.z + y1.z), leaky(x1.w + y1.w),
                leaky(x2.x + y2.x), leaky(x2.y + y2.y), leaky(x2.z + y2.z), leaky(x2.w + y2.w)};
            #pragma unroll
            for (int q = 0; q < 12; q++) {
                const int d = ch * 12 + q;
                float4 w0 = s_w2[d * 3 + 0], w1 = s_w2[d * 3 + 1], w2v = s_w2[d * 3 + 2];
                const float hv = h[q];
                acc[0] = fmaf(hv, w0.x, acc[0]); acc[1] = fmaf(hv, w0.y, acc[1]);
                acc[2] = fmaf(hv, w0.z, acc[2]); acc[3] = fmaf(hv, w0.w, acc[3]);
                acc[4] = fmaf(hv, w1.x, acc[4]); acc[5] = fmaf(hv, w1.y, acc[5]);
                acc[6] = fmaf(hv, w1.z, acc[6]); acc[7] = fmaf(hv, w1.w, acc[7]);
                acc[8] = fmaf(hv, w2v.x, acc[8]); acc[9] = fmaf(hv, w2v.y, acc[9]);
            }
        }

        // leaky + softmax (in-thread)
        float m = -1e30f;
        #pragma unroll
        for (int c = 0; c < PC; c++) { acc[c] = leaky(acc[c]); m = fmaxf(m, acc[c]); }
        float sum = 0.f;
        #pragma unroll
        for (int c = 0; c < PC; c++) { acc[c] = __expf(acc[c] - m); sum += acc[c]; }
        const float is = 1.f / sum;
        #pragma unroll
        for (int c = 0; c < PC; c++) acc[c] *= is;

        float4* amr = reinterpret_cast<float4*>(&nodes[nl].am[k][0]);
        amr[0] = make_float4(acc[0], acc[1], acc[2], acc[3]);
        amr[1] = make_float4(acc[4], acc[5], acc[6], acc[7]);
        amr[2] = make_float4(acc[8], acc[9], 0.f, 0.f);

        // gather wh_k, inv-norm, diagonal dist
        const float4* wp = reinterpret_cast<const float4*>(&g_wh[(size_t)jn * S_OUT]);
        float4 b0 = wp[0], b1 = wp[1], b2v = wp[2];
        float n2 = b0.x * b0.x;
        n2 = fmaf(b0.y, b0.y, n2); n2 = fmaf(b0.z, b0.z, n2); n2 = fmaf(b0.w, b0.w, n2);
        n2 = fmaf(b1.x, b1.x, n2); n2 = fmaf(b1.y, b1.y, n2); n2 = fmaf(b1.z, b1.z, n2);
        n2 = fmaf(b1.w, b1.w, n2); n2 = fmaf(b2v.x, b2v.x, n2); n2 = fmaf(b2v.y, b2v.y, n2);
        n2 = fmaf(b2v.z, b2v.z, n2); n2 = fmaf(b2v.w, b2v.w, n2);
        const float inv = 1.f / (sqrtf(n2) + 1e-8f);

        float4* whr = reinterpret_cast<float4*>(&nodes[nl].wh[k][0]);
        whr[0] = b0; whr[1] = b1; whr[2] = b2v;
        nodes[nl].inv[k] = inv;
        ddsum = (double)(n2 * inv * inv);
    }
    __syncthreads();

    // ================= phase 2a: output, thread = (node, c, half) ==========
    {
        const int r = tid - nl * PK;        // 0..19
        const int c = r >> 1, half = r & 1;
        const NodeS& M = nodes[nl];
        const float* amp = &M.am[0][c];              // stride 12
        const float* whp = &M.wh[0][half * 6];       // stride 20, 8B aligned

        float o0 = 0.f, o1 = 0.f, o2 = 0.f, o3 = 0.f, o4 = 0.f, o5 = 0.f;
        #pragma unroll
        for (int kk = 0; kk < PK; kk++) {
            const float a = amp[kk * 12];
            float2 u0 = *reinterpret_cast<const float2*>(whp + kk * 20);
            float2 u1 = *reinterpret_cast<const float2*>(whp + kk * 20 + 2);
            float2 u2 = *reinterpret_cast<const float2*>(whp + kk * 20 + 4);
            o0 = fmaf(a, u0.x, o0); o1 = fmaf(a, u0.y, o1);
            o2 = fmaf(a, u1.x, o2); o3 = fmaf(a, u1.y, o3);
            o4 = fmaf(a, u2.x, o4); o5 = fmaf(a, u2.y, o5);
        }
        float* op = out + (size_t)node * (PC * S_OUT) + c * S_OUT + half * 6;
        *reinterpret_cast<float2*>(op + 0) = make_float2(o0, o1);
        *reinterpret_cast<float2*>(op + 2) = make_float2(o2, o3);
        *reinterpret_cast<float2*>(op + 4) = make_float2(o4, o5);
    }

    // ================= phase 2b: triangle pairs (x2 each) ==================
    float fcl = 0.f, fds = 0.f;
    {
        int n = 0, p = tid;                 // tid < 160 < 190
        #pragma unroll 1
        for (int item = tid; item < NODES_PER_CTA * NPAIRS; item += MAIN_THREADS) {
            const NodeS& M = nodes[n];
            const unsigned tpk = s_tbl[p];
            const int kk = tpk >> 5, ll = tpk & 31;

            const float4* rk = reinterpret_cast<const float4*>(&M.wh[kk][0]);
            const float4* rl = reinterpret_cast<const float4*>(&M.wh[ll][0]);
            float4 k0 = rk[0], k1 = rk[1], k2 = rk[2];
            float4 l0 = rl[0], l1 = rl[1], l2 = rl[2];
            float dot = k0.x * l0.x;
            dot = fmaf(k0.y, l0.y, dot); dot = fmaf(k0.z, l0.z, dot);
            dot = fmaf(k0.w, l0.w, dot); dot = fmaf(k1.x, l1.x, dot);
            dot = fmaf(k1.y, l1.y, dot); dot = fmaf(k1.z, l1.z, dot);
            dot = fmaf(k1.w, l1.w, dot); dot = fmaf(k2.x, l2.x, dot);
            dot = fmaf(k2.y, l2.y, dot); dot = fmaf(k2.z, l2.z, dot);
            dot = fmaf(k2.w, l2.w, dot);
            const float dist = dot * M.inv[kk] * M.inv[ll];
            fds += dist;

            const float4* ak = reinterpret_cast<const float4*>(&M.am[kk][0]);
            const float4* al = reinterpret_cast<const float4*>(&M.am[ll][0]);
            float4 p0 = ak[0], p1 = ak[1], p2 = ak[2];
            float4 q0 = al[0], q1 = al[1], q2 = al[2];
            float prob = p0.x * q0.x;
            prob = fmaf(p0.y, q0.y, prob); prob = fmaf(p0.z, q0.z, prob);
            prob = fmaf(p0.w, q0.w, prob); prob = fmaf(p1.x, q1.x, prob);
            prob = fmaf(p1.y, q1.y, prob); prob = fmaf(p1.z, q1.z, prob);
            prob = fmaf(p1.w, q1.w, prob); prob = fmaf(p2.x, q2.x, prob);
            prob = fmaf(p2.y, q2.y, prob);          // zero pads
            prob = fminf(fmaxf(prob, 1e-4f), 1.f - 1e-4f);
            const float lg = __logf(prob);
            fcl += (dist >= 0.5f) ? -lg : lg;

            p += MAIN_THREADS;
            if (p >= NPAIRS) { p -= NPAIRS; n++; }
        }
    }

    // ---- reduce: warp -> block -> global atomics; last CTA finalizes ------
    double clsum = 2.0 * (double)fcl;
    double dsum  = 2.0 * (double)fds + ddsum;
    #pragma unroll
    for (int o = 16; o > 0; o >>= 1) {
        clsum += __shfl_down_sync(0xffffffffu, clsum, o);
        dsum  += __shfl_down_sync(0xffffffffu, dsum,  o);
    }
    if (lane == 0) { s_redc[wid] = clsum; s_redd[wid] = dsum; }
    __syncthreads();

    if (tid == 0) {
        double tc = 0.0, td = 0.0;
        #pragma unroll
        for (int q = 0; q < 5; q++) { tc += s_redc[q]; td += s_redd[q]; }
        atomicAdd(&g_acc[0], tc);
        atomicAdd(&g_acc[1], td);
        __threadfence();
        unsigned int done = atomicAdd(&g_done, 1u);
        if (done == (unsigned int)(gridDim.x - 1)) {
            __threadfence();
            volatile double* acc = g_acc;
            double c0 = acc[0], c1 = acc[1], c2 = acc[2];
            out[OUT_DATA_ELEMS + 0] = (float)(c0 / (double)BN);
            out[OUT_DATA_ELEMS + 1] = (float)(c1 / ((double)BN * PK * PK));
            out[OUT_DATA_ELEMS + 2] = (float)(c2 / ((double)BN * S_OUT));
            acc[0] = 0.0; acc[1] = 0.0; acc[2] = 0.0;
            g_done = 0;
            __threadfence();
        }
    }
}

// ---------------- launch ----------------
extern "C" void kernel_launch(void* const* d_in, const int* in_sizes, int n_in,
                              void* d_out, int out_size)
{
    const float* input_data = (const float*)d_in[1];
    const float* wW  = (const float*)d_in[2];
    const float* wb  = (const float*)d_in[3];
    const float* a1W = (const float*)d_in[4];
    const float* a1b = (const float*)d_in[5];
    const float* a2W = (const float*)d_in[6];
    const float* a2b = (const float*)d_in[7];
    const int*   idx = (const int*)d_in[8];
    float* out = (float*)d_out;

    k_pre <<<(BN + 63) / 64, 128>>>(input_data, wW, wb, a1W, a1b);
    k_main<<<MAIN_CTAS, MAIN_THREADS>>>(idx, a2W, a2b, out);
}

// round 12
// speedup vs baseline: 1.3495x; 1.0907x over previous
#include <cuda_runtime.h>
#include <math.h>

// Problem constants
#define PB     32
#define PN     325
#define PK     20
#define S_IN   12
#define S_OUT  12
#define PC     10
#define H48    48
#define BN     (PB * PN)                 // 10400 nodes
#define OUT_DATA_ELEMS (BN * PC * S_OUT) // 1,248,000

#define NODES_PER_CTA  8
#define MAIN_THREADS   160               // 8 nodes * 20 k-slots, 5 warps
#define MAIN_CTAS      (BN / NODES_PER_CTA)   // 1300
#define NPAIRS         190               // K*(K-1)/2 triangle pairs

// ---------------- scratch (no allocation allowed) ----------------
__device__ __align__(16) float  g_wh [BN * S_OUT];   // wh per node (12)
__device__ __align__(16) float  g_hxb[BN * H48];     // hx + a1_b per node (48)
__device__ double g_acc[3];        // 0: cluster-loss sum, 1: dist sum, 2: wh sum
__device__ unsigned int g_done;    // last-block counter (self-resetting)

__device__ __forceinline__ float leaky(float x) { return x >= 0.f ? x : 0.5f * x; }

// ---- packed f32x2 helpers (FFMA2 is PTX-only) ----
typedef unsigned long long u64q;
__device__ __forceinline__ u64q pk2(float a, float b) {
    u64q r; asm("mov.b64 %0,{%1,%2};" : "=l"(r) : "f"(a), "f"(b)); return r;
}
__device__ __forceinline__ void upk2(u64q v, float& a, float& b) {
    asm("mov.b64 {%0,%1},%2;" : "=f"(a), "=f"(b) : "l"(v));
}
__device__ __forceinline__ u64q fma2(u64q a, u64q b, u64q c) {
    u64q d; asm("fma.rn.f32x2 %0,%1,%2,%3;" : "=l"(d) : "l"(a), "l"(b), "l"(c)); return d;
}

// ---------------- kernel 1: per-node precompute (wh + hx only) ----------------
// 2 threads per node (24 of 48 hidden dims each); 64 nodes per 128-thread CTA.
__global__ void __launch_bounds__(128)
k_pre(const float* __restrict__ in,
      const float* __restrict__ wW,  const float* __restrict__ wb,
      const float* __restrict__ a1W, const float* __restrict__ a1b)
{
    __shared__ float s_wW[S_IN * S_OUT];
    __shared__ float s_wb[S_OUT];
    __shared__ float s_a1W[S_OUT * H48];     // only first half (hx)
    __shared__ float s_a1b[H48];
    __shared__ double s_red[4];

    for (int i = threadIdx.x; i < S_IN * S_OUT; i += 128) s_wW[i]  = wW[i];
    if (threadIdx.x < S_OUT) s_wb[threadIdx.x] = wb[threadIdx.x];
    for (int i = threadIdx.x; i < S_OUT * H48;  i += 128) s_a1W[i] = a1W[i];
    if (threadIdx.x < H48) s_a1b[threadIdx.x] = a1b[threadIdx.x];
    __syncthreads();

    const int t    = threadIdx.x;
    const int node = blockIdx.x * 64 + (t >> 1);
    const int half = t & 1;
    float whsum = 0.f;

    if (node < BN) {
        const float4* xp = reinterpret_cast<const float4*>(&in[node * S_IN]);
        float4 x0 = xp[0], x1 = xp[1], x2 = xp[2];
        float x[S_IN] = {x0.x, x0.y, x0.z, x0.w, x1.x, x1.y, x1.z, x1.w,
                         x2.x, x2.y, x2.z, x2.w};

        float wh[S_OUT];
        #pragma unroll
        for (int j = 0; j < S_OUT; j++) {
            float a = s_wb[j];
            #pragma unroll
            for (int i = 0; i < S_IN; i++) a = fmaf(x[i], s_wW[i * S_OUT + j], a);
            wh[j] = leaky(a);
        }
        if (half == 0) {
            float4* wp = reinterpret_cast<float4*>(&g_wh[(size_t)node * S_OUT]);
            wp[0] = make_float4(wh[0], wh[1], wh[2], wh[3]);
            wp[1] = make_float4(wh[4], wh[5], wh[6], wh[7]);
            wp[2] = make_float4(wh[8], wh[9], wh[10], wh[11]);
            #pragma unroll
            for (int j = 0; j < S_OUT; j++) whsum += wh[j];
        }

        const int d0 = half * 24;
        #pragma unroll
        for (int dq = 0; dq < 24; dq += 4) {
            float hx[4];
            #pragma unroll
            for (int q = 0; q < 4; q++) {
                int d = d0 + dq + q;
                float a = s_a1b[d];
                #pragma unroll
                for (int j = 0; j < S_OUT; j++)
                    a = fmaf(wh[j], s_a1W[j * H48 + d], a);
                hx[q] = a;
            }
            *reinterpret_cast<float4*>(&g_hxb[(size_t)node * H48 + d0 + dq]) =
                make_float4(hx[0], hx[1], hx[2], hx[3]);
        }
    }

    #pragma unroll
    for (int o = 16; o > 0; o >>= 1) whsum += __shfl_down_sync(0xffffffffu, whsum, o);
    int warp = threadIdx.x >> 5, lane = threadIdx.x & 31;
    if (lane == 0) s_red[warp] = (double)whsum;
    __syncthreads();
    if (threadIdx.x == 0)
        atomicAdd(&g_acc[2], s_red[0] + s_red[1] + s_red[2] + s_red[3]);
}

// ---------------- kernel 2: thread-per-(node,k) main, hy recomputed ----------------
struct __align__(16) NodeS {
    float wh [PK][20];   // 12 data + pad to 20 floats
    float am [PK][12];   // 10 data + 2 zero pads
    float inv[PK];
};

__global__ void __launch_bounds__(MAIN_THREADS, 8)
k_main(const int* __restrict__ idx,
       const float* __restrict__ a1W,
       const float* __restrict__ a2W, const float* __restrict__ a2b,
       float* __restrict__ out)
{
    __shared__ NodeS nodes[NODES_PER_CTA];                 // ~21 KB
    __shared__ __align__(16) float s_w2y[H48][12];         // a1_W[12:] transposed: [d][j]
    __shared__ __align__(16) float s_w2a[H48][12];         // a2_W rows padded 10->12
    __shared__ float  s_b2[PC];
    __shared__ float4 s_hx4[NODES_PER_CTA * 12];           // hx rows for the 8 nodes
    __shared__ unsigned short s_tbl[NPAIRS];               // packed (k<<5)|l, k<l
    __shared__ double s_redc[5], s_redd[5];

    const int tid  = threadIdx.x;
    const int wid  = tid >> 5;
    const int lane = tid & 31;
    const int nl   = tid / PK;            // 0..7 node-local
    const int k    = tid - nl * PK;       // 0..19
    const int node = blockIdx.x * NODES_PER_CTA + nl;
    const int base = (node / PN) * PN;

    // ---- stage weights, bias, pair table, hx rows ----
    for (int i = tid; i < H48 * 12; i += MAIN_THREADS) {
        int d = i / 12, j = i - d * 12;
        s_w2y[d][j] = a1W[(S_OUT + j) * H48 + d];
        s_w2a[d][j] = (j < PC) ? a2W[d * PC + j] : 0.f;
    }
    if (tid < PC) s_b2[tid] = a2b[tid];
    for (int i = tid; i < NPAIRS; i += MAIN_THREADS) {
        int kk = 0, rem = i;
        while (rem >= PK - 1 - kk) { rem -= PK - 1 - kk; kk++; }
        s_tbl[i] = (unsigned short)((kk << 5) | (kk + 1 + rem));
    }
    for (int i = tid; i < NODES_PER_CTA * 12; i += MAIN_THREADS) {
        int n = i / 12, q = i - n * 12;
        s_hx4[i] = reinterpret_cast<const float4*>(
            g_hxb + (size_t)(blockIdx.x * NODES_PER_CTA + n) * H48)[q];
    }
    __syncthreads();

    double ddsum = 0.0;   // diagonal dist contribution

    // ================= phase 1: one thread = one (node, k) =================
    {
        const int jn = base + idx[node * PK + k];

        // gather neighbor wh (only gather in the kernel): 3 LDG.128
        const float4* wp = reinterpret_cast<const float4*>(&g_wh[(size_t)jn * S_OUT]);
        float4 wa = wp[0], wbv = wp[1], wc = wp[2];

        // pack wh into 6 f32x2 registers
        u64q whp[6] = { pk2(wa.x, wa.y), pk2(wa.z, wa.w),
                        pk2(wbv.x, wbv.y), pk2(wbv.z, wbv.w),
                        pk2(wc.x, wc.y), pk2(wc.z, wc.w) };

        // norm + store row (serves pair phase)
        float n2 = wa.x * wa.x;
        n2 = fmaf(wa.y, wa.y, n2); n2 = fmaf(wa.z, wa.z, n2); n2 = fmaf(wa.w, wa.w, n2);
        n2 = fmaf(wbv.x, wbv.x, n2); n2 = fmaf(wbv.y, wbv.y, n2); n2 = fmaf(wbv.z, wbv.z, n2);
        n2 = fmaf(wbv.w, wbv.w, n2); n2 = fmaf(wc.x, wc.x, n2); n2 = fmaf(wc.y, wc.y, n2);
        n2 = fmaf(wc.z, wc.z, n2); n2 = fmaf(wc.w, wc.w, n2);
        const float inv = 1.f / (sqrtf(n2) + 1e-8f);
        float4* whr = reinterpret_cast<float4*>(&nodes[nl].wh[k][0]);
        whr[0] = wa; whr[1] = wbv; whr[2] = wc;
        nodes[nl].inv[k] = inv;
        ddsum = (double)(n2 * inv * inv);

        // packed attention accumulators initialized with bias
        u64q acc[5] = { pk2(s_b2[0], s_b2[1]), pk2(s_b2[2], s_b2[3]),
                        pk2(s_b2[4], s_b2[5]), pk2(s_b2[6], s_b2[7]),
                        pk2(s_b2[8], s_b2[9]) };
        const u64q zero2 = pk2(0.f, 0.f);

        #pragma unroll
        for (int ch = 0; ch < 12; ch++) {
            float4 hx4 = s_hx4[nl * 12 + ch];
            float hxv[4] = { hx4.x, hx4.y, hx4.z, hx4.w };
            #pragma unroll
            for (int q = 0; q < 4; q++) {
                const int d = ch * 4 + q;
                // hy_d = wh . w2y[d][:]  (packed, 6 FFMA2)
                const float4* yr = reinterpret_cast<const float4*>(&s_w2y[d][0]);
                float4 y0 = yr[0], y1 = yr[1], y2 = yr[2];
                u64q hs = fma2(whp[0], pk2(y0.x, y0.y), zero2);
                hs = fma2(whp[1], pk2(y0.z, y0.w), hs);
                hs = fma2(whp[2], pk2(y1.x, y1.y), hs);
                hs = fma2(whp[3], pk2(y1.z, y1.w), hs);
                hs = fma2(whp[4], pk2(y2.x, y2.y), hs);
                hs = fma2(whp[5], pk2(y2.z, y2.w), hs);
                float hlo, hhi; upk2(hs, hlo, hhi);
                const float h = leaky(hxv[q] + (hlo + hhi));
                const u64q hh = pk2(h, h);
                // acc_c += h * w2a[d][c]  (packed, 5 FFMA2)
                const float4* ar = reinterpret_cast<const float4*>(&s_w2a[d][0]);
                float4 a0 = ar[0], a1 = ar[1], a2v = ar[2];
                acc[0] = fma2(hh, pk2(a0.x, a0.y), acc[0]);
                acc[1] = fma2(hh, pk2(a0.z, a0.w), acc[1]);
                acc[2] = fma2(hh, pk2(a1.x, a1.y), acc[2]);
                acc[3] = fma2(hh, pk2(a1.z, a1.w), acc[3]);
                acc[4] = fma2(hh, pk2(a2v.x, a2v.y), acc[4]);
            }
        }

        // unpack, leaky + softmax
        float av[PC];
        upk2(acc[0], av[0], av[1]); upk2(acc[1], av[2], av[3]);
        upk2(acc[2], av[4], av[5]); upk2(acc[3], av[6], av[7]);
        upk2(acc[4], av[8], av[9]);
        float m = -1e30f;
        #pragma unroll
        for (int c = 0; c < PC; c++) { av[c] = leaky(av[c]); m = fmaxf(m, av[c]); }
        float sum = 0.f;
        #pragma unroll
        for (int c = 0; c < PC; c++) { av[c] = __expf(av[c] - m); sum += av[c]; }
        const float is = 1.f / sum;
        #pragma unroll
        for (int c = 0; c < PC; c++) av[c] *= is;

        float4* amr = reinterpret_cast<float4*>(&nodes[nl].am[k][0]);
        amr[0] = make_float4(av[0], av[1], av[2], av[3]);
        amr[1] = make_float4(av[4], av[5], av[6], av[7]);
        amr[2] = make_float4(av[8], av[9], 0.f, 0.f);
    }
    __syncthreads();

    // ================= phase 2a: output, thread = (node, c, half) ==========
    {
        const int r = tid - nl * PK;        // 0..19
        const int c = r >> 1, half = r & 1;
        const NodeS& M = nodes[nl];
        const float* amp = &M.am[0][c];              // stride 12
        const float* whp2 = &M.wh[0][half * 6];      // stride 20, 8B aligned

        float o0 = 0.f, o1 = 0.f, o2 = 0.f, o3 = 0.f, o4 = 0.f, o5 = 0.f;
        #pragma unroll
        for (int kk = 0; kk < PK; kk++) {
            const float a = amp[kk * 12];
            float2 u0 = *reinterpret_cast<const float2*>(whp2 + kk * 20);
            float2 u1 = *reinterpret_cast<const float2*>(whp2 + kk * 20 + 2);
            float2 u2 = *reinterpret_cast<const float2*>(whp2 + kk * 20 + 4);
            o0 = fmaf(a, u0.x, o0); o1 = fmaf(a, u0.y, o1);
            o2 = fmaf(a, u1.x, o2); o3 = fmaf(a, u1.y, o3);
            o4 = fmaf(a, u2.x, o4); o5 = fmaf(a, u2.y, o5);
        }
        float* op = out + (size_t)node * (PC * S_OUT) + c * S_OUT + half * 6;
        *reinterpret_cast<float2*>(op + 0) = make_float2(o0, o1);
        *reinterpret_cast<float2*>(op + 2) = make_float2(o2, o3);
        *reinterpret_cast<float2*>(op + 4) = make_float2(o4, o5);
    }

    // ================= phase 2b: triangle pairs (x2 each) ==================
    float fcl = 0.f, fds = 0.f;
    {
        int n = 0, p = tid;                 // tid < 160 < 190
        #pragma unroll 1
        for (int item = tid; item < NODES_PER_CTA * NPAIRS; item += MAIN_THREADS) {
            const NodeS& M = nodes[n];
            const unsigned tpk = s_tbl[p];
            const int kk = tpk >> 5, ll = tpk & 31;

            const float4* rk = reinterpret_cast<const float4*>(&M.wh[kk][0]);
            const float4* rl = reinterpret_cast<const float4*>(&M.wh[ll][0]);
            float4 k0 = rk[0], k1 = rk[1], k2 = rk[2];
            float4 l0 = rl[0], l1 = rl[1], l2 = rl[2];
            float dot = k0.x * l0.x;
            dot = fmaf(k0.y, l0.y, dot); dot = fmaf(k0.z, l0.z, dot);
            dot = fmaf(k0.w, l0.w, dot); dot = fmaf(k1.x, l1.x, dot);
            dot = fmaf(k1.y, l1.y, dot); dot = fmaf(k1.z, l1.z, dot);
            dot = fmaf(k1.w, l1.w, dot); dot = fmaf(k2.x, l2.x, dot);
            dot = fmaf(k2.y, l2.y, dot); dot = fmaf(k2.z, l2.z, dot);
            dot = fmaf(k2.w, l2.w, dot);
            const float dist = dot * M.inv[kk] * M.inv[ll];
            fds += dist;

            const float4* ak = reinterpret_cast<const float4*>(&M.am[kk][0]);
            const float4* al = reinterpret_cast<const float4*>(&M.am[ll][0]);
            float4 p0 = ak[0], p1 = ak[1], p2 = ak[2];
            float4 q0 = al[0], q1 = al[1], q2 = al[2];
            float prob = p0.x * q0.x;
            prob = fmaf(p0.y, q0.y, prob); prob = fmaf(p0.z, q0.z, prob);
            prob = fmaf(p0.w, q0.w, prob); prob = fmaf(p1.x, q1.x, prob);
            prob = fmaf(p1.y, q1.y, prob); prob = fmaf(p1.z, q1.z, prob);
            prob = fmaf(p1.w, q1.w, prob); prob = fmaf(p2.x, q2.x, prob);
            prob = fmaf(p2.y, q2.y, prob);          // zero pads
            prob = fminf(fmaxf(prob, 1e-4f), 1.f - 1e-4f);
            const float lg = __logf(prob);
            fcl += (dist >= 0.5f) ? -lg : lg;

            p += MAIN_THREADS;
            if (p >= NPAIRS) { p -= NPAIRS; n++; }
        }
    }

    // ---- reduce: warp -> block -> global atomics; last CTA finalizes ------
    double clsum = 2.0 * (double)fcl;
    double dsum  = 2.0 * (double)fds + ddsum;
    #pragma unroll
    for (int o = 16; o > 0; o >>= 1) {
        clsum += __shfl_down_sync(0xffffffffu, clsum, o);
        dsum  += __shfl_down_sync(0xffffffffu, dsum,  o);
    }
    if (lane == 0) { s_redc[wid] = clsum; s_redd[wid] = dsum; }
    __syncthreads();

    if (tid == 0) {
        double tc = 0.0, td = 0.0;
        #pragma unroll
        for (int q = 0; q < 5; q++) { tc += s_redc[q]; td += s_redd[q]; }
        atomicAdd(&g_acc[0], tc);
        atomicAdd(&g_acc[1], td);
        __threadfence();
        unsigned int done = atomicAdd(&g_done, 1u);
        if (done == (unsigned int)(gridDim.x - 1)) {
            __threadfence();
            volatile double* acc = g_acc;
            double c0 = acc[0], c1 = acc[1], c2 = acc[2];
            out[OUT_DATA_ELEMS + 0] = (float)(c0 / (double)BN);
            out[OUT_DATA_ELEMS + 1] = (float)(c1 / ((double)BN * PK * PK));
            out[OUT_DATA_ELEMS + 2] = (float)(c2 / ((double)BN * S_OUT));
            acc[0] = 0.0; acc[1] = 0.0; acc[2] = 0.0;
            g_done = 0;
            __threadfence();
        }
    }
}

// ---------------- launch ----------------
extern "C" void kernel_launch(void* const* d_in, const int* in_sizes, int n_in,
                              void* d_out, int out_size)
{
    const float* input_data = (const float*)d_in[1];
    const float* wW  = (const float*)d_in[2];
    const float* wb  = (const float*)d_in[3];
    const float* a1W = (const float*)d_in[4];
    const float* a1b = (const float*)d_in[5];
    const float* a2W = (const float*)d_in[6];
    const float* a2b = (const float*)d_in[7];
    const int*   idx = (const int*)d_in[8];
    float* out = (float*)d_out;

    k_pre <<<(BN + 63) / 64, 128>>>(input_data, wW, wb, a1W, a1b);
    k_main<<<MAIN_CTAS, MAIN_THREADS>>>(idx, a1W, a2W, a2b, out);
}